// round 6
// baseline (speedup 1.0000x reference)
#include <cuda_runtime.h>
#include <cuda_bf16.h>
#include <cstdint>
#include <cstddef>

#define N_ROWS 500000
#define D_IN   128
#define R_DIM  256
#define D_OUT  64
#define U_DIM  10000
#define EPS    1e-8f
#define BM     128         // rows per block
#define NTHR   512         // 16 warps

// ---------------- precomputed weights (bf16, [n][k] layout) -----------------
__device__ __nv_bfloat16 g_w0mh[R_DIM * D_IN];
__device__ __nv_bfloat16 g_w0ml[R_DIM * D_IN];
__device__ __nv_bfloat16 g_w0vh[R_DIM * D_IN];
__device__ __nv_bfloat16 g_w1mh[D_OUT * R_DIM];
__device__ __nv_bfloat16 g_w1ml[D_OUT * R_DIM];
__device__ __nv_bfloat16 g_w1a1[D_OUT * R_DIM];
__device__ __nv_bfloat16 g_w1vh[D_OUT * R_DIM];
__device__ float g_sum_inv[U_DIM * D_OUT];
__device__ float g_sum_minv[U_DIM * D_OUT];

// ---------------- smem layout (bytes) ---------------------------------------
#define P0B 272
#define P1B 80
#define S_XH     0                     // 128*272 = 34816
#define S_XL     34816
#define S_X2H    69632
#define S_W0     104448                // 2 stages x 3 mats x 32*272
#define W0_STAGE 26112
#define W0_MAT   8704
#define S_W1     156672                // 4 mats x 64*80
#define W1_MAT   5120
#define S_L1MH   177152                // 128*80 each
#define S_L1ML   187392
#define S_L1VH   197632
#define S_L12H   207872
#define S_UID    218112                // 128*4
#define SMEM_SZ  218624
#define S_SINV   0                     // staging overlays X (post-GEMM)
#define S_SMINV  34816

// ---------------- helpers ----------------------------------------------------
static __device__ __forceinline__ uint32_t smem_u32(const void* p) {
    uint32_t a;
    asm("{ .reg .u64 t; cvta.to.shared.u64 t, %1; cvt.u32.u64 %0, t; }"
        : "=r"(a) : "l"(p));
    return a;
}
#define LDSM4(R, addr) \
    asm volatile("ldmatrix.sync.aligned.m8n8.x4.shared.b16 {%0,%1,%2,%3}, [%4];" \
        : "=r"((R)[0]), "=r"((R)[1]), "=r"((R)[2]), "=r"((R)[3]) : "r"(addr))
#define CP16(s, g) \
    asm volatile("cp.async.cg.shared.global [%0], [%1], 16;" :: "r"(s), "l"(g))
#define CP_COMMIT() asm volatile("cp.async.commit_group;" ::: "memory")
#define CP_WAIT(N)  asm volatile("cp.async.wait_group %0;" :: "n"(N) : "memory")

static __device__ __forceinline__ void mma16816(float* c, const uint32_t* a,
                                                const uint32_t* b) {
    asm volatile("mma.sync.aligned.m16n8k16.row.col.f32.bf16.bf16.f32 "
                 "{%0,%1,%2,%3},{%4,%5,%6,%7},{%8,%9},{%0,%1,%2,%3};"
                 : "+f"(c[0]), "+f"(c[1]), "+f"(c[2]), "+f"(c[3])
                 : "r"(a[0]), "r"(a[1]), "r"(a[2]), "r"(a[3]),
                   "r"(b[0]), "r"(b[1]));
}
static __device__ __forceinline__ void split2(float x, __nv_bfloat16& h,
                                              __nv_bfloat16& l) {
    h = __float2bfloat16(x);
    l = __float2bfloat16(x - __bfloat162float(h));
}
static __device__ __forceinline__ uint32_t pk(__nv_bfloat16 a, __nv_bfloat16 b) {
    return (uint32_t)__bfloat16_as_ushort(a) | ((uint32_t)__bfloat16_as_ushort(b) << 16);
}

// ---------------- prep -------------------------------------------------------
__global__ __launch_bounds__(256) void prep_kernel(const float* __restrict__ Wmu0,
                                                   const float* __restrict__ Wlv0,
                                                   const float* __restrict__ Wmu1,
                                                   const float* __restrict__ Wlv1) {
    int id = blockIdx.x * 256 + threadIdx.x;
    if (id < R_DIM * D_IN) {
        int n = id >> 7, k = id & 127;
        float wm = Wmu0[(size_t)k * R_DIM + n];
        float wv = expf(Wlv0[(size_t)k * R_DIM + n]);
        __nv_bfloat16 h, l;
        split2(wm, h, l);
        g_w0mh[id] = h;
        g_w0ml[id] = l;
        g_w0vh[id] = __float2bfloat16(wv);
    }
    if (id < D_OUT * R_DIM) {
        int n = id >> 8, k = id & 255;
        float wm = Wmu1[(size_t)k * D_OUT + n];
        float e  = expf(Wlv1[(size_t)k * D_OUT + n]);
        __nv_bfloat16 h, l;
        split2(wm, h, l);
        g_w1mh[id] = h;
        g_w1ml[id] = l;
        g_w1a1[id] = __float2bfloat16(wm * wm + e);
        g_w1vh[id] = __float2bfloat16(e);
    }
    if (id < U_DIM * D_OUT) { g_sum_inv[id] = 0.f; g_sum_minv[id] = 0.f; }
}

// ============================================================================
// Fused kernel: 128 rows/block, 512 threads, warp grid 8(m) x 2(n).
// 8 weight chunks of 32; W0 double-buffered + cp.async pipelined.
// ============================================================================
__global__ __launch_bounds__(NTHR, 1) void fused_kernel(const float* __restrict__ X,
                                                        const int* __restrict__ X_idx) {
    extern __shared__ char sm[];
    const uint32_t sb = smem_u32(sm);
    const int t = threadIdx.x, lane = t & 31, wid = t >> 5;
    const int wm_ = wid >> 1, wn = wid & 1;           // 8 x 2
    const int rowBase = blockIdx.x * BM;
    const int lr = lane & 7, sel = lane >> 3;

    // ---- prefetch W0[0] into stage 0 (512 slots = 32 rows x 16 units) -------
    {
        int r = t >> 4, kk = t & 15;
        uint32_t so = sb + S_W0 + r * P0B + kk * 16;
        size_t go = (size_t)r * D_IN + kk * 8;
        CP16(so,              (const char*)&g_w0mh[go]);
        CP16(so + W0_MAT,     (const char*)&g_w0ml[go]);
        CP16(so + 2 * W0_MAT, (const char*)&g_w0vh[go]);
    }
    CP_COMMIT();

    if (t < BM) {
        int r = rowBase + t;
        *(int*)(sm + S_UID + t * 4) = (r < N_ROWS) ? X_idx[r] : -1;
    }

    // ---- phase 0: X tile 128 x 128 -> xh / xl / x2h --------------------------
    #pragma unroll
    for (int it = 0; it < 8; it++) {
        int idx = t + it * NTHR;
        int row = idx >> 5;
        int k4  = (idx & 31) * 4;
        float4 v = make_float4(0.f, 0.f, 0.f, 0.f);
        if (rowBase + row < N_ROWS)
            v = *(const float4*)&X[(size_t)(rowBase + row) * D_IN + k4];
        const float xs[4] = {v.x, v.y, v.z, v.w};
        __nv_bfloat16 h[4], l[4], q[4];
        #pragma unroll
        for (int e = 0; e < 4; e++) {
            split2(xs[e], h[e], l[e]);
            q[e] = __float2bfloat16(xs[e] * xs[e]);
        }
        int o = row * P0B + k4 * 2;
        *(uint32_t*)(sm + S_XH  + o)     = pk(h[0], h[1]);
        *(uint32_t*)(sm + S_XH  + o + 4) = pk(h[2], h[3]);
        *(uint32_t*)(sm + S_XL  + o)     = pk(l[0], l[1]);
        *(uint32_t*)(sm + S_XL  + o + 4) = pk(l[2], l[3]);
        *(uint32_t*)(sm + S_X2H + o)     = pk(q[0], q[1]);
        *(uint32_t*)(sm + S_X2H + o + 4) = pk(q[2], q[3]);
    }

    float accM1[4][4], accV1[4][4];
    #pragma unroll
    for (int b = 0; b < 4; b++)
        #pragma unroll
        for (int c = 0; c < 4; c++) { accM1[b][c] = 0.f; accV1[b][c] = 0.f; }

    for (int nc = 0; nc < 8; nc++) {
        // ---- issue W1[nc] (single buffer, 256 slots = 64 rows x 4 units) -----
        if (t < 256) {
            int row = t >> 2, k16 = t & 3;
            size_t go = (size_t)row * R_DIM + nc * 32 + k16 * 8;
            uint32_t so = sb + S_W1 + row * P1B + k16 * 16;
            CP16(so,              (const char*)&g_w1mh[go]);
            CP16(so + W1_MAT,     (const char*)&g_w1ml[go]);
            CP16(so + 2 * W1_MAT, (const char*)&g_w1a1[go]);
            CP16(so + 3 * W1_MAT, (const char*)&g_w1vh[go]);
        }
        CP_COMMIT();
        // ---- issue W0[nc+1] into stage (nc+1)&1 ------------------------------
        if (nc < 7) {
            uint32_t base = sb + S_W0 + ((nc + 1) & 1) * W0_STAGE;
            int r = t >> 4, kk = t & 15;
            size_t go = (size_t)((nc + 1) * 32 + r) * D_IN + kk * 8;
            uint32_t so = base + r * P0B + kk * 16;
            CP16(so,              (const char*)&g_w0mh[go]);
            CP16(so + W0_MAT,     (const char*)&g_w0ml[go]);
            CP16(so + 2 * W0_MAT, (const char*)&g_w0vh[go]);
        }
        CP_COMMIT();

        CP_WAIT(2);                      // W0[nc] arrived
        __syncthreads();

        // ---- layer0 MMA for this 32-col chunk (M 3-term, V 1-term) -----------
        // warp tile: m=16 (wm_), n=16 (wn)
        const uint32_t w0b = sb + S_W0 + (nc & 1) * W0_STAGE;
        float aM[2][4], aV[2][4];
        #pragma unroll
        for (int b = 0; b < 2; b++)
            #pragma unroll
            for (int c = 0; c < 4; c++) { aM[b][c] = 0.f; aV[b][c] = 0.f; }

        #pragma unroll
        for (int ks = 0; ks < 8; ks++) {
            const int k = ks * 16;
            uint32_t Axh[4], Axl[4], A2h[4];
            {
                int ar = wm_ * 16 + lr + (sel & 1) * 8;
                int ac = k + (sel >> 1) * 8;
                uint32_t off = (uint32_t)(ar * P0B + ac * 2);
                LDSM4(Axh, sb + S_XH + off);
                LDSM4(Axl, sb + S_XL + off);
                LDSM4(A2h, sb + S_X2H + off);
            }
            uint32_t Bmh[4], Bml[4], Bvh[4];
            {
                int br = wn * 16 + lr + (sel >> 1) * 8;
                int bc = k + (sel & 1) * 8;
                uint32_t off = (uint32_t)(br * P0B + bc * 2);
                LDSM4(Bmh, w0b + off);
                LDSM4(Bml, w0b + W0_MAT + off);
                LDSM4(Bvh, w0b + 2 * W0_MAT + off);
            }
            #pragma unroll
            for (int cq = 0; cq < 2; cq++) {
                int o2 = cq * 2;
                mma16816(aM[cq], Axh, &Bmh[o2]);
                mma16816(aM[cq], Axh, &Bml[o2]);
                mma16816(aM[cq], Axl, &Bmh[o2]);
                mma16816(aV[cq], A2h, &Bvh[o2]);
            }
        }

        // ---- gate + split into layer1 A buffers -------------------------------
        #pragma unroll
        for (int cq = 0; cq < 2; cq++) {
            int klocal = wn * 16 + cq * 8 + 2 * (lane & 3);
            #pragma unroll
            for (int half = 0; half < 2; half++) {
                int lrow = wm_ * 16 + (lane >> 2) + half * 8;
                float m0 = aM[cq][half * 2 + 0];
                float m1 = aM[cq][half * 2 + 1];
                float v0 = aV[cq][half * 2 + 0];
                float v1 = aV[cq][half * 2 + 1];
                bool g0 = m0 > 0.f, g1 = m1 > 0.f;
                m0 = g0 ? m0 : 0.f;  v0 = g0 ? v0 : 0.f;
                m1 = g1 ? m1 : 0.f;  v1 = g1 ? v1 : 0.f;
                __nv_bfloat16 h0, l0, h1, l1;
                split2(m0, h0, l0);
                split2(m1, h1, l1);
                int o = lrow * P1B + klocal * 2;
                *(uint32_t*)(sm + S_L1MH + o) = pk(h0, h1);
                *(uint32_t*)(sm + S_L1ML + o) = pk(l0, l1);
                *(uint32_t*)(sm + S_L1VH + o) =
                    pk(__float2bfloat16(v0), __float2bfloat16(v1));
                *(uint32_t*)(sm + S_L12H + o) =
                    pk(__float2bfloat16(m0 * m0), __float2bfloat16(m1 * m1));
            }
        }

        CP_WAIT(1);                      // W1[nc] arrived (W0[nc+1] may still fly)
        __syncthreads();

        // ---- layer1 MMA accumulate (M 3-term, V 2-term) ------------------------
        // warp tile: m=16 (wm_), n=32 (wn of 2)
        #pragma unroll
        for (int ks = 0; ks < 2; ks++) {
            const int k = ks * 16;
            uint32_t Amh[4], Aml[4], Avh[4], A2m[4];
            {
                int ar = wm_ * 16 + lr + (sel & 1) * 8;
                int ac = k + (sel >> 1) * 8;
                uint32_t off = (uint32_t)(ar * P1B + ac * 2);
                LDSM4(Amh, sb + S_L1MH + off);
                LDSM4(Aml, sb + S_L1ML + off);
                LDSM4(Avh, sb + S_L1VH + off);
                LDSM4(A2m, sb + S_L12H + off);
            }
            uint32_t Bm[2][4], Bl[2][4], Ba[2][4], Bv[2][4];
            #pragma unroll
            for (int p = 0; p < 2; p++) {
                int br = wn * 32 + p * 16 + lr + (sel >> 1) * 8;
                int bc = k + (sel & 1) * 8;
                uint32_t off = (uint32_t)(br * P1B + bc * 2);
                LDSM4(Bm[p], sb + S_W1 + off);
                LDSM4(Bl[p], sb + S_W1 + W1_MAT + off);
                LDSM4(Ba[p], sb + S_W1 + 2 * W1_MAT + off);
                LDSM4(Bv[p], sb + S_W1 + 3 * W1_MAT + off);
            }
            #pragma unroll
            for (int p = 0; p < 2; p++) {
                #pragma unroll
                for (int cq = 0; cq < 2; cq++) {
                    int cf = p * 2 + cq, o2 = cq * 2;
                    mma16816(accM1[cf], Amh, &Bm[p][o2]);
                    mma16816(accM1[cf], Amh, &Bl[p][o2]);
                    mma16816(accM1[cf], Aml, &Bm[p][o2]);
                    mma16816(accV1[cf], Avh, &Ba[p][o2]);
                    mma16816(accV1[cf], A2m, &Bv[p][o2]);
                }
            }
        }
        __syncthreads();                 // W1 + L1A buffers free for next chunk
    }

    // ---- epilogue: inv-variance weighting into smem staging --------------------
    float* sInv  = (float*)(sm + S_SINV);
    float* sMinv = (float*)(sm + S_SMINV);
    #pragma unroll
    for (int cf = 0; cf < 4; cf++) {
        int col = wn * 32 + cf * 8 + 2 * (lane & 3);
        #pragma unroll
        for (int half = 0; half < 2; half++) {
            int lrow = wm_ * 16 + (lane >> 2) + half * 8;
            float m0 = accM1[cf][half * 2 + 0];
            float m1 = accM1[cf][half * 2 + 1];
            float V0 = fmaxf(accV1[cf][half * 2 + 0], EPS);
            float V1 = fmaxf(accV1[cf][half * 2 + 1], EPS);
            float i0 = 1.f / V0, i1 = 1.f / V1;
            sInv[lrow * 65 + col]      = i0;
            sInv[lrow * 65 + col + 1]  = i1;
            sMinv[lrow * 65 + col]     = m0 * i0;
            sMinv[lrow * 65 + col + 1] = m1 * i1;
        }
    }
    __syncthreads();

    // ---- block-level segmented reduce over sorted uids -> atomics ---------------
    const int* uids = (const int*)(sm + S_UID);
    int col = t & 63, grp = t >> 6;            // 8 groups x 16 rows
    float aI = 0.f, aM = 0.f;
    int cur = -1;
    for (int r0 = 0; r0 < 16; r0++) {
        int row = grp * 16 + r0;
        int uid = uids[row];
        if (uid != cur) {
            if (cur >= 0) {
                atomicAdd(&g_sum_inv[cur * D_OUT + col], aI);
                atomicAdd(&g_sum_minv[cur * D_OUT + col], aM);
            }
            cur = uid; aI = 0.f; aM = 0.f;
        }
        if (uid >= 0) {
            aI += sInv[row * 65 + col];
            aM += sMinv[row * 65 + col];
        }
    }
    if (cur >= 0) {
        atomicAdd(&g_sum_inv[cur * D_OUT + col], aI);
        atomicAdd(&g_sum_minv[cur * D_OUT + col], aM);
    }
}

// ---------------- finalize ----------------------------------------------------
__global__ __launch_bounds__(256) void finalize_kernel(float* __restrict__ out) {
    int id = blockIdx.x * 256 + threadIdx.x;
    if (id < U_DIM * D_OUT) {
        float var = 1.f / (g_sum_inv[id] + EPS);
        out[id]                 = g_sum_minv[id] * var;
        out[U_DIM * D_OUT + id] = var;
    }
}

// ---------------- launch -------------------------------------------------------
extern "C" void kernel_launch(void* const* d_in, const int* in_sizes, int n_in,
                              void* d_out, int out_size) {
    const float* X     = (const float*)d_in[0];
    const int*   X_idx = (const int*)d_in[1];
    const float* Wmu0  = (const float*)d_in[2];
    const float* Wlv0  = (const float*)d_in[3];
    const float* Wmu1  = (const float*)d_in[4];
    const float* Wlv1  = (const float*)d_in[5];
    float* out = (float*)d_out;
    (void)in_sizes; (void)n_in; (void)out_size;

    cudaFuncSetAttribute(fused_kernel, cudaFuncAttributeMaxDynamicSharedMemorySize,
                         SMEM_SZ);

    const int nBlocks = (N_ROWS + BM - 1) / BM;

    prep_kernel<<<(U_DIM * D_OUT + 255) / 256, 256>>>(Wmu0, Wlv0, Wmu1, Wlv1);
    fused_kernel<<<nBlocks, NTHR, SMEM_SZ>>>(X, X_idx);
    finalize_kernel<<<(U_DIM * D_OUT + 255) / 256, 256>>>(out);
}

// round 7
// speedup vs baseline: 1.1192x; 1.1192x over previous
#include <cuda_runtime.h>
#include <cuda_bf16.h>
#include <cstdint>
#include <cstddef>

#define N_ROWS 500000
#define D_IN   128
#define R_DIM  256
#define D_OUT  64
#define U_DIM  10000
#define EPS    1e-8f
#define BM     64          // rows per block
#define NTHR   256         // 8 warps

// ---------------- precomputed weights (bf16, [n][k] layout) -----------------
__device__ __nv_bfloat16 g_w0mh[R_DIM * D_IN];
__device__ __nv_bfloat16 g_w0ml[R_DIM * D_IN];
__device__ __nv_bfloat16 g_w0vh[R_DIM * D_IN];
__device__ __nv_bfloat16 g_w1mh[D_OUT * R_DIM];
__device__ __nv_bfloat16 g_w1ml[D_OUT * R_DIM];
__device__ __nv_bfloat16 g_w1a1[D_OUT * R_DIM];
__device__ __nv_bfloat16 g_w1vh[D_OUT * R_DIM];
__device__ float g_sum_inv[U_DIM * D_OUT];
__device__ float g_sum_minv[U_DIM * D_OUT];

// ---------------- smem layout (bytes), pitch 272 everywhere ------------------
// X mats: 64 rows x 272B.  W0: 3 mats x 32 x 272.  W1/L1A: 4 mats interleaved
// per row ([mh|ml|a1|vh] 4x64B + 16B pad = 272B/row).
#define P0B     272
#define S_XH    0
#define S_XL    17408
#define S_X2H   34816
#define S_W0    52224
#define W0_MAT  8704
#define S_W1    78336
#define S_L1A   95744
#define S_UID   113152
#define SMEM_SZ 113408
#define S_SINV  0           // staging overlays X (post-GEMM)
#define S_SMINV 17408

// ---------------- helpers ----------------------------------------------------
static __device__ __forceinline__ uint32_t smem_u32(const void* p) {
    uint32_t a;
    asm("{ .reg .u64 t; cvta.to.shared.u64 t, %1; cvt.u32.u64 %0, t; }"
        : "=r"(a) : "l"(p));
    return a;
}
#define LDSM4(R, addr) \
    asm volatile("ldmatrix.sync.aligned.m8n8.x4.shared.b16 {%0,%1,%2,%3}, [%4];" \
        : "=r"((R)[0]), "=r"((R)[1]), "=r"((R)[2]), "=r"((R)[3]) : "r"(addr))
#define CP16(s, g) \
    asm volatile("cp.async.cg.shared.global [%0], [%1], 16;" :: "r"(s), "l"(g))
#define CP_COMMIT() asm volatile("cp.async.commit_group;" ::: "memory")
#define CP_WAIT(N)  asm volatile("cp.async.wait_group %0;" :: "n"(N) : "memory")

static __device__ __forceinline__ void mma16816(float* c, const uint32_t* a,
                                                const uint32_t* b) {
    asm volatile("mma.sync.aligned.m16n8k16.row.col.f32.bf16.bf16.f32 "
                 "{%0,%1,%2,%3},{%4,%5,%6,%7},{%8,%9},{%0,%1,%2,%3};"
                 : "+f"(c[0]), "+f"(c[1]), "+f"(c[2]), "+f"(c[3])
                 : "r"(a[0]), "r"(a[1]), "r"(a[2]), "r"(a[3]),
                   "r"(b[0]), "r"(b[1]));
}
static __device__ __forceinline__ void split2(float x, __nv_bfloat16& h,
                                              __nv_bfloat16& l) {
    h = __float2bfloat16(x);
    l = __float2bfloat16(x - __bfloat162float(h));
}
static __device__ __forceinline__ uint32_t pk(__nv_bfloat16 a, __nv_bfloat16 b) {
    return (uint32_t)__bfloat16_as_ushort(a) | ((uint32_t)__bfloat16_as_ushort(b) << 16);
}

// ---------------- prep -------------------------------------------------------
__global__ __launch_bounds__(256) void prep_kernel(const float* __restrict__ Wmu0,
                                                   const float* __restrict__ Wlv0,
                                                   const float* __restrict__ Wmu1,
                                                   const float* __restrict__ Wlv1) {
    int id = blockIdx.x * 256 + threadIdx.x;
    if (id < R_DIM * D_IN) {
        int n = id >> 7, k = id & 127;
        float wm = Wmu0[(size_t)k * R_DIM + n];
        float wv = expf(Wlv0[(size_t)k * R_DIM + n]);
        __nv_bfloat16 h, l;
        split2(wm, h, l);
        g_w0mh[id] = h;
        g_w0ml[id] = l;
        g_w0vh[id] = __float2bfloat16(wv);
    }
    if (id < D_OUT * R_DIM) {
        int n = id >> 8, k = id & 255;
        float wm = Wmu1[(size_t)k * D_OUT + n];
        float e  = expf(Wlv1[(size_t)k * D_OUT + n]);
        __nv_bfloat16 h, l;
        split2(wm, h, l);
        g_w1mh[id] = h;
        g_w1ml[id] = l;
        g_w1a1[id] = __float2bfloat16(wm * wm + e);
        g_w1vh[id] = __float2bfloat16(e);
    }
    if (id < U_DIM * D_OUT) { g_sum_inv[id] = 0.f; g_sum_minv[id] = 0.f; }
}

// ============================================================================
// Fused kernel: 64 rows/block, 256 threads (8 warps, grid 4m x 2n), 2 CTAs/SM.
// 8 weight chunks of 32; W0 single-buffered (cross-CTA overlap hides latency).
// ============================================================================
__global__ __launch_bounds__(NTHR, 2) void fused_kernel(const float* __restrict__ X,
                                                        const int* __restrict__ X_idx) {
    extern __shared__ char sm[];
    const uint32_t sb = smem_u32(sm);
    const int t = threadIdx.x, lane = t & 31, wid = t >> 5;
    const int wm_ = wid >> 1, wn = wid & 1;           // 4 x 2
    const int rowBase = blockIdx.x * BM;
    const int lr = lane & 7, sel = lane >> 3;

    // ---- prefetch W0[0] (32 rows x 16 units x 3 mats) ------------------------
    #pragma unroll
    for (int it = 0; it < 2; it++) {
        int idx = t + it * NTHR;
        int r = idx >> 4, kk = idx & 15;
        uint32_t so = sb + S_W0 + r * P0B + kk * 16;
        size_t go = (size_t)r * D_IN + kk * 8;
        CP16(so,              (const char*)&g_w0mh[go]);
        CP16(so + W0_MAT,     (const char*)&g_w0ml[go]);
        CP16(so + 2 * W0_MAT, (const char*)&g_w0vh[go]);
    }
    CP_COMMIT();

    if (t < BM) {
        int r = rowBase + t;
        *(int*)(sm + S_UID + t * 4) = (r < N_ROWS) ? X_idx[r] : -1;
    }

    // ---- X tile 64 x 128 -> xh / xl / x2h -------------------------------------
    #pragma unroll
    for (int it = 0; it < 8; it++) {
        int idx = t + it * NTHR;
        int row = idx >> 5;
        int k4  = (idx & 31) * 4;
        float4 v = make_float4(0.f, 0.f, 0.f, 0.f);
        if (rowBase + row < N_ROWS)
            v = *(const float4*)&X[(size_t)(rowBase + row) * D_IN + k4];
        const float xs[4] = {v.x, v.y, v.z, v.w};
        __nv_bfloat16 h[4], l[4], q[4];
        #pragma unroll
        for (int e = 0; e < 4; e++) {
            split2(xs[e], h[e], l[e]);
            q[e] = __float2bfloat16(xs[e] * xs[e]);
        }
        int o = row * P0B + k4 * 2;
        *(uint32_t*)(sm + S_XH  + o)     = pk(h[0], h[1]);
        *(uint32_t*)(sm + S_XH  + o + 4) = pk(h[2], h[3]);
        *(uint32_t*)(sm + S_XL  + o)     = pk(l[0], l[1]);
        *(uint32_t*)(sm + S_XL  + o + 4) = pk(l[2], l[3]);
        *(uint32_t*)(sm + S_X2H + o)     = pk(q[0], q[1]);
        *(uint32_t*)(sm + S_X2H + o + 4) = pk(q[2], q[3]);
    }

    float accM1[4][4], accV1[4][4];
    #pragma unroll
    for (int b = 0; b < 4; b++)
        #pragma unroll
        for (int c = 0; c < 4; c++) { accM1[b][c] = 0.f; accV1[b][c] = 0.f; }

    for (int nc = 0; nc < 8; nc++) {
        // ---- issue W1[nc]: 64 rows x 4 units x 4 mats (interleaved) ----------
        {
            int row = t >> 2, k16 = t & 3;
            size_t go = (size_t)row * R_DIM + nc * 32 + k16 * 8;
            uint32_t so = sb + S_W1 + row * P0B + k16 * 16;
            CP16(so,       (const char*)&g_w1mh[go]);
            CP16(so + 64,  (const char*)&g_w1ml[go]);
            CP16(so + 128, (const char*)&g_w1a1[go]);
            CP16(so + 192, (const char*)&g_w1vh[go]);
        }
        CP_COMMIT();
        CP_WAIT(1);                      // W0[nc] arrived
        __syncthreads();                 // (1) W0/X visible; W1/L1A free

        // ---- layer0 MMA: warp tile 16(m) x 16(n); M 3-term, V 1-term ----------
        float aM[2][4], aV[2][4];
        #pragma unroll
        for (int b = 0; b < 2; b++)
            #pragma unroll
            for (int c = 0; c < 4; c++) { aM[b][c] = 0.f; aV[b][c] = 0.f; }

        #pragma unroll
        for (int ks = 0; ks < 8; ks++) {
            const int k = ks * 16;
            uint32_t Axh[4], Axl[4], A2h[4];
            {
                int ar = wm_ * 16 + lr + (sel & 1) * 8;
                int ac = k + (sel >> 1) * 8;
                uint32_t off = (uint32_t)(ar * P0B + ac * 2);
                LDSM4(Axh, sb + S_XH + off);
                LDSM4(Axl, sb + S_XL + off);
                LDSM4(A2h, sb + S_X2H + off);
            }
            uint32_t Bmh[4], Bml[4], Bvh[4];
            {
                int br = wn * 16 + lr + (sel >> 1) * 8;
                int bc = k + (sel & 1) * 8;
                uint32_t off = (uint32_t)(br * P0B + bc * 2);
                LDSM4(Bmh, sb + S_W0 + off);
                LDSM4(Bml, sb + S_W0 + W0_MAT + off);
                LDSM4(Bvh, sb + S_W0 + 2 * W0_MAT + off);
            }
            #pragma unroll
            for (int cq = 0; cq < 2; cq++) {
                int o2 = cq * 2;
                mma16816(aM[cq], Axh, &Bmh[o2]);
                mma16816(aM[cq], Axh, &Bml[o2]);
                mma16816(aM[cq], Axl, &Bmh[o2]);
                mma16816(aV[cq], A2h, &Bvh[o2]);
            }
        }

        // ---- gate + split into interleaved L1A --------------------------------
        #pragma unroll
        for (int cq = 0; cq < 2; cq++) {
            int klocal = wn * 16 + cq * 8 + 2 * (lane & 3);
            #pragma unroll
            for (int half = 0; half < 2; half++) {
                int lrow = wm_ * 16 + (lane >> 2) + half * 8;
                float m0 = aM[cq][half * 2 + 0];
                float m1 = aM[cq][half * 2 + 1];
                float v0 = aV[cq][half * 2 + 0];
                float v1 = aV[cq][half * 2 + 1];
                bool g0 = m0 > 0.f, g1 = m1 > 0.f;
                m0 = g0 ? m0 : 0.f;  v0 = g0 ? v0 : 0.f;
                m1 = g1 ? m1 : 0.f;  v1 = g1 ? v1 : 0.f;
                __nv_bfloat16 h0, l0, h1, l1;
                split2(m0, h0, l0);
                split2(m1, h1, l1);
                int o = lrow * P0B + klocal * 2;
                *(uint32_t*)(sm + S_L1A + o)       = pk(h0, h1);
                *(uint32_t*)(sm + S_L1A + o + 64)  = pk(l0, l1);
                *(uint32_t*)(sm + S_L1A + o + 128) =
                    pk(__float2bfloat16(v0), __float2bfloat16(v1));
                *(uint32_t*)(sm + S_L1A + o + 192) =
                    pk(__float2bfloat16(m0 * m0), __float2bfloat16(m1 * m1));
            }
        }

        CP_WAIT(0);                      // W1[nc] fully arrived
        __syncthreads();                 // (2) L1A+W1 visible; W0 buffer free

        // ---- issue W0[nc+1] into the single buffer ----------------------------
        if (nc < 7) {
            #pragma unroll
            for (int it = 0; it < 2; it++) {
                int idx = t + it * NTHR;
                int r = idx >> 4, kk = idx & 15;
                size_t go = (size_t)((nc + 1) * 32 + r) * D_IN + kk * 8;
                uint32_t so = sb + S_W0 + r * P0B + kk * 16;
                CP16(so,              (const char*)&g_w0mh[go]);
                CP16(so + W0_MAT,     (const char*)&g_w0ml[go]);
                CP16(so + 2 * W0_MAT, (const char*)&g_w0vh[go]);
            }
        }
        CP_COMMIT();

        // ---- layer1 MMA: warp tile 16(m) x 32(n); M 3-term, V 2-term ----------
        #pragma unroll
        for (int ks = 0; ks < 2; ks++) {
            const int k = ks * 16;
            uint32_t Amh[4], Aml[4], Avh[4], A2m[4];
            {
                int ar = wm_ * 16 + lr + (sel & 1) * 8;
                int ac = k + (sel >> 1) * 8;
                uint32_t off = (uint32_t)(ar * P0B + ac * 2);
                LDSM4(Amh, sb + S_L1A + off);
                LDSM4(Aml, sb + S_L1A + 64 + off);
                LDSM4(Avh, sb + S_L1A + 128 + off);
                LDSM4(A2m, sb + S_L1A + 192 + off);
            }
            #pragma unroll
            for (int p = 0; p < 2; p++) {
                uint32_t Bm[4], Bl[4], Ba[4], Bv[4];
                int br = wn * 32 + p * 16 + lr + (sel >> 1) * 8;
                int bc = k + (sel & 1) * 8;
                uint32_t off = (uint32_t)(br * P0B + bc * 2);
                LDSM4(Bm, sb + S_W1 + off);
                LDSM4(Bl, sb + S_W1 + 64 + off);
                LDSM4(Ba, sb + S_W1 + 128 + off);
                LDSM4(Bv, sb + S_W1 + 192 + off);
                #pragma unroll
                for (int cq = 0; cq < 2; cq++) {
                    int cf = p * 2 + cq, o2 = cq * 2;
                    mma16816(accM1[cf], Amh, &Bm[o2]);
                    mma16816(accM1[cf], Amh, &Bl[o2]);
                    mma16816(accM1[cf], Aml, &Bm[o2]);
                    mma16816(accV1[cf], Avh, &Ba[o2]);
                    mma16816(accV1[cf], A2m, &Bv[o2]);
                }
            }
        }
        __syncthreads();                 // (3) W1/L1A free for next chunk
    }

    // ---- epilogue: inv-variance weighting into smem staging (overlays X) -------
    float* sInv  = (float*)(sm + S_SINV);
    float* sMinv = (float*)(sm + S_SMINV);
    #pragma unroll
    for (int cf = 0; cf < 4; cf++) {
        int col = wn * 32 + cf * 8 + 2 * (lane & 3);
        #pragma unroll
        for (int half = 0; half < 2; half++) {
            int lrow = wm_ * 16 + (lane >> 2) + half * 8;
            float m0 = accM1[cf][half * 2 + 0];
            float m1 = accM1[cf][half * 2 + 1];
            float V0 = fmaxf(accV1[cf][half * 2 + 0], EPS);
            float V1 = fmaxf(accV1[cf][half * 2 + 1], EPS);
            float i0 = 1.f / V0, i1 = 1.f / V1;
            sInv[lrow * 65 + col]      = i0;
            sInv[lrow * 65 + col + 1]  = i1;
            sMinv[lrow * 65 + col]     = m0 * i0;
            sMinv[lrow * 65 + col + 1] = m1 * i1;
        }
    }
    __syncthreads();

    // ---- block-level segmented reduce over sorted uids -> atomics ---------------
    const int* uids = (const int*)(sm + S_UID);
    int col = t & 63, grp = t >> 6;            // 4 groups x 16 rows
    float aI = 0.f, aM = 0.f;
    int cur = -1;
    for (int r0 = 0; r0 < 16; r0++) {
        int row = grp * 16 + r0;
        int uid = uids[row];
        if (uid != cur) {
            if (cur >= 0) {
                atomicAdd(&g_sum_inv[cur * D_OUT + col], aI);
                atomicAdd(&g_sum_minv[cur * D_OUT + col], aM);
            }
            cur = uid; aI = 0.f; aM = 0.f;
        }
        if (uid >= 0) {
            aI += sInv[row * 65 + col];
            aM += sMinv[row * 65 + col];
        }
    }
    if (cur >= 0) {
        atomicAdd(&g_sum_inv[cur * D_OUT + col], aI);
        atomicAdd(&g_sum_minv[cur * D_OUT + col], aM);
    }
}

// ---------------- finalize ----------------------------------------------------
__global__ __launch_bounds__(256) void finalize_kernel(float* __restrict__ out) {
    int id = blockIdx.x * 256 + threadIdx.x;
    if (id < U_DIM * D_OUT) {
        float var = 1.f / (g_sum_inv[id] + EPS);
        out[id]                 = g_sum_minv[id] * var;
        out[U_DIM * D_OUT + id] = var;
    }
}

// ---------------- launch -------------------------------------------------------
extern "C" void kernel_launch(void* const* d_in, const int* in_sizes, int n_in,
                              void* d_out, int out_size) {
    const float* X     = (const float*)d_in[0];
    const int*   X_idx = (const int*)d_in[1];
    const float* Wmu0  = (const float*)d_in[2];
    const float* Wlv0  = (const float*)d_in[3];
    const float* Wmu1  = (const float*)d_in[4];
    const float* Wlv1  = (const float*)d_in[5];
    float* out = (float*)d_out;
    (void)in_sizes; (void)n_in; (void)out_size;

    cudaFuncSetAttribute(fused_kernel, cudaFuncAttributeMaxDynamicSharedMemorySize,
                         SMEM_SZ);

    const int nBlocks = (N_ROWS + BM - 1) / BM;

    prep_kernel<<<(U_DIM * D_OUT + 255) / 256, 256>>>(Wmu0, Wlv0, Wmu1, Wlv1);
    fused_kernel<<<nBlocks, NTHR, SMEM_SZ>>>(X, X_idx);
    finalize_kernel<<<(U_DIM * D_OUT + 255) / 256, 256>>>(out);
}

// round 10
// speedup vs baseline: 1.3285x; 1.1871x over previous
#include <cuda_runtime.h>
#include <cuda_bf16.h>
#include <cstdint>
#include <cstddef>

#define N_ROWS 500000
#define D_IN   128
#define R_DIM  256
#define D_OUT  64
#define U_DIM  10000
#define EPS    1e-8f
#define BM     128         // rows per block
#define NTHR   256         // 8 warps

// ---------------- precomputed weights (bf16, [n][k] layout) -----------------
__device__ __nv_bfloat16 g_w0mh[R_DIM * D_IN];
__device__ __nv_bfloat16 g_w0ml[R_DIM * D_IN];
__device__ __nv_bfloat16 g_w0vh[R_DIM * D_IN];
__device__ __nv_bfloat16 g_w1mh[D_OUT * R_DIM];
__device__ __nv_bfloat16 g_w1ml[D_OUT * R_DIM];
__device__ __nv_bfloat16 g_w1a1[D_OUT * R_DIM];
__device__ __nv_bfloat16 g_w1vh[D_OUT * R_DIM];
__device__ float g_sum_inv[U_DIM * D_OUT];
__device__ float g_sum_minv[U_DIM * D_OUT];

// ---------------- smem layout (bytes) ---------------------------------------
#define P0B 272
#define P1B 80
#define S_XH     0                     // 128*272 = 34816
#define S_X2H    34816
#define S_W0     69632                 // 2 stages x 3 mats x 32*272
#define W0_STAGE 26112
#define W0_MAT   8704
#define S_W1     121856                // 4 mats x 64*80 = 20480
#define W1_MAT   5120
#define S_L1MH   142336                // 128*80 each
#define S_L1VH   152576
#define S_L12H   162816
#define S_UID    173056                // 128*4
#define SMEM_SZ  173568
#define S_SINV   0                     // staging overlays XH (post-GEMM)
#define S_SMINV  34816                 // overlays X2H

// ---------------- helpers ----------------------------------------------------
static __device__ __forceinline__ uint32_t smem_u32(const void* p) {
    uint32_t a;
    asm("{ .reg .u64 t; cvta.to.shared.u64 t, %1; cvt.u32.u64 %0, t; }"
        : "=r"(a) : "l"(p));
    return a;
}
#define LDSM4(R, addr) \
    asm volatile("ldmatrix.sync.aligned.m8n8.x4.shared.b16 {%0,%1,%2,%3}, [%4];" \
        : "=r"((R)[0]), "=r"((R)[1]), "=r"((R)[2]), "=r"((R)[3]) : "r"(addr))
#define CP16(s, g) \
    asm volatile("cp.async.cg.shared.global [%0], [%1], 16;" :: "r"(s), "l"(g))
#define CP_COMMIT() asm volatile("cp.async.commit_group;" ::: "memory")
#define CP_WAIT(N)  asm volatile("cp.async.wait_group %0;" :: "n"(N) : "memory")

static __device__ __forceinline__ void mma16816(float* c, const uint32_t* a,
                                                const uint32_t* b) {
    asm volatile("mma.sync.aligned.m16n8k16.row.col.f32.bf16.bf16.f32 "
                 "{%0,%1,%2,%3},{%4,%5,%6,%7},{%8,%9},{%0,%1,%2,%3};"
                 : "+f"(c[0]), "+f"(c[1]), "+f"(c[2]), "+f"(c[3])
                 : "r"(a[0]), "r"(a[1]), "r"(a[2]), "r"(a[3]),
                   "r"(b[0]), "r"(b[1]));
}
static __device__ __forceinline__ void split2(float x, __nv_bfloat16& h,
                                              __nv_bfloat16& l) {
    h = __float2bfloat16(x);
    l = __float2bfloat16(x - __bfloat162float(h));
}
static __device__ __forceinline__ uint32_t pk(__nv_bfloat16 a, __nv_bfloat16 b) {
    return (uint32_t)__bfloat16_as_ushort(a) | ((uint32_t)__bfloat16_as_ushort(b) << 16);
}

// ---------------- prep -------------------------------------------------------
__global__ __launch_bounds__(256) void prep_kernel(const float* __restrict__ Wmu0,
                                                   const float* __restrict__ Wlv0,
                                                   const float* __restrict__ Wmu1,
                                                   const float* __restrict__ Wlv1) {
    int id = blockIdx.x * 256 + threadIdx.x;
    if (id < R_DIM * D_IN) {
        int n = id >> 7, k = id & 127;
        float wm = Wmu0[(size_t)k * R_DIM + n];
        float wv = expf(Wlv0[(size_t)k * R_DIM + n]);
        __nv_bfloat16 h, l;
        split2(wm, h, l);
        g_w0mh[id] = h;
        g_w0ml[id] = l;
        g_w0vh[id] = __float2bfloat16(wv);
    }
    if (id < D_OUT * R_DIM) {
        int n = id >> 8, k = id & 255;
        float wm = Wmu1[(size_t)k * D_OUT + n];
        float e  = expf(Wlv1[(size_t)k * D_OUT + n]);
        __nv_bfloat16 h, l;
        split2(wm, h, l);
        g_w1mh[id] = h;
        g_w1ml[id] = l;
        g_w1a1[id] = __float2bfloat16(wm * wm + e);
        g_w1vh[id] = __float2bfloat16(e);
    }
    if (id < U_DIM * D_OUT) { g_sum_inv[id] = 0.f; g_sum_minv[id] = 0.f; }
}

// ============================================================================
// Fused kernel: 128 rows/block, 256 threads, warp grid 4(m) x 2(n).
// 8 weight chunks of 32; W0 double-buffered + cp.async pipelined.
// Term scheme (weight-lo kept — systematic; activation-lo dropped — random):
//   L0 M = xh*(w0mh+w0ml), L0 V = x2h*w0vh,
//   L1 M = mh*(w1mh+w1ml), L1 V = vh*a1h + m2h*w1vh.
// ============================================================================
__global__ __launch_bounds__(NTHR, 1) void fused_kernel(const float* __restrict__ X,
                                                        const int* __restrict__ X_idx) {
    extern __shared__ char sm[];
    const uint32_t sb = smem_u32(sm);
    const int t = threadIdx.x, lane = t & 31, wid = t >> 5;
    const int wm_ = wid >> 1, wn = wid & 1;
    const int rowBase = blockIdx.x * BM;
    const int lr = lane & 7, sel = lane >> 3;

    // ---- prefetch W0[0] into stage 0 (512 slots = 32 rows x 16 units) --------
    #pragma unroll
    for (int it = 0; it < 2; it++) {
        int idx = t + it * NTHR;
        int r = idx >> 4, kk = idx & 15;
        uint32_t so = sb + S_W0 + r * P0B + kk * 16;
        size_t go = (size_t)r * D_IN + kk * 8;
        CP16(so,              (const char*)&g_w0mh[go]);
        CP16(so + W0_MAT,     (const char*)&g_w0ml[go]);
        CP16(so + 2 * W0_MAT, (const char*)&g_w0vh[go]);
    }
    CP_COMMIT();

    if (t < BM) {
        int r = rowBase + t;
        *(int*)(sm + S_UID + t * 4) = (r < N_ROWS) ? X_idx[r] : -1;
    }

    // ---- phase 0: X tile 128 x 128 -> xh / x2h --------------------------------
    #pragma unroll
    for (int it = 0; it < 16; it++) {
        int idx = t + it * NTHR;
        int row = idx >> 5;
        int k4  = (idx & 31) * 4;
        float4 v = make_float4(0.f, 0.f, 0.f, 0.f);
        if (rowBase + row < N_ROWS)
            v = *(const float4*)&X[(size_t)(rowBase + row) * D_IN + k4];
        const float xs[4] = {v.x, v.y, v.z, v.w};
        __nv_bfloat16 h[4], q[4];
        #pragma unroll
        for (int e = 0; e < 4; e++) {
            h[e] = __float2bfloat16(xs[e]);
            q[e] = __float2bfloat16(xs[e] * xs[e]);
        }
        int o = row * P0B + k4 * 2;
        *(uint32_t*)(sm + S_XH  + o)     = pk(h[0], h[1]);
        *(uint32_t*)(sm + S_XH  + o + 4) = pk(h[2], h[3]);
        *(uint32_t*)(sm + S_X2H + o)     = pk(q[0], q[1]);
        *(uint32_t*)(sm + S_X2H + o + 4) = pk(q[2], q[3]);
    }

    float accM1[2][4][4], accV1[2][4][4];
    #pragma unroll
    for (int a = 0; a < 2; a++)
        #pragma unroll
        for (int b = 0; b < 4; b++)
            #pragma unroll
            for (int c = 0; c < 4; c++) { accM1[a][b][c] = 0.f; accV1[a][b][c] = 0.f; }

    for (int nc = 0; nc < 8; nc++) {
        // ---- issue W1[nc] (single buffer, 4 mats, 256 slots) ------------------
        {
            int row = t >> 2, k16 = t & 3;
            size_t go = (size_t)row * R_DIM + nc * 32 + k16 * 8;
            uint32_t so = sb + S_W1 + row * P1B + k16 * 16;
            CP16(so,              (const char*)&g_w1mh[go]);
            CP16(so + W1_MAT,     (const char*)&g_w1ml[go]);
            CP16(so + 2 * W1_MAT, (const char*)&g_w1a1[go]);
            CP16(so + 3 * W1_MAT, (const char*)&g_w1vh[go]);
        }
        CP_COMMIT();
        // ---- issue W0[nc+1] into stage (nc+1)&1 -------------------------------
        if (nc < 7) {
            uint32_t base = sb + S_W0 + ((nc + 1) & 1) * W0_STAGE;
            #pragma unroll
            for (int it = 0; it < 2; it++) {
                int idx = t + it * NTHR;
                int r = idx >> 4, kk = idx & 15;
                size_t go = (size_t)((nc + 1) * 32 + r) * D_IN + kk * 8;
                uint32_t so = base + r * P0B + kk * 16;
                CP16(so,              (const char*)&g_w0mh[go]);
                CP16(so + W0_MAT,     (const char*)&g_w0ml[go]);
                CP16(so + 2 * W0_MAT, (const char*)&g_w0vh[go]);
            }
        }
        CP_COMMIT();

        CP_WAIT(2);                      // W0[nc] arrived
        __syncthreads();

        // ---- layer0 MMA for this 32-col chunk ----------------------------------
        const uint32_t w0b = sb + S_W0 + (nc & 1) * W0_STAGE;
        float aM[2][2][4], aV[2][2][4];
        #pragma unroll
        for (int a = 0; a < 2; a++)
            #pragma unroll
            for (int b = 0; b < 2; b++)
                #pragma unroll
                for (int c = 0; c < 4; c++) { aM[a][b][c] = 0.f; aV[a][b][c] = 0.f; }

        #pragma unroll
        for (int ks = 0; ks < 8; ks++) {
            const int k = ks * 16;
            uint32_t Axh[2][4], A2h[2][4];
            #pragma unroll
            for (int rf = 0; rf < 2; rf++) {
                int ar = wm_ * 32 + rf * 16 + lr + (sel & 1) * 8;
                int ac = k + (sel >> 1) * 8;
                uint32_t off = (uint32_t)(ar * P0B + ac * 2);
                LDSM4(Axh[rf], sb + S_XH + off);
                LDSM4(A2h[rf], sb + S_X2H + off);
            }
            uint32_t Bmh[4], Bml[4], Bvh[4];
            {
                int br = wn * 16 + lr + (sel >> 1) * 8;
                int bc = k + (sel & 1) * 8;
                uint32_t off = (uint32_t)(br * P0B + bc * 2);
                LDSM4(Bmh, w0b + off);
                LDSM4(Bml, w0b + W0_MAT + off);
                LDSM4(Bvh, w0b + 2 * W0_MAT + off);
            }
            #pragma unroll
            for (int rf = 0; rf < 2; rf++) {
                #pragma unroll
                for (int cq = 0; cq < 2; cq++) {
                    int o2 = cq * 2;
                    mma16816(aM[rf][cq], Axh[rf], &Bmh[o2]);
                    mma16816(aM[rf][cq], Axh[rf], &Bml[o2]);
                    mma16816(aV[rf][cq], A2h[rf], &Bvh[o2]);
                }
            }
        }

        // ---- gate + convert into layer1 A buffers (mh / vh / m2h) --------------
        #pragma unroll
        for (int rf = 0; rf < 2; rf++) {
            #pragma unroll
            for (int cq = 0; cq < 2; cq++) {
                int klocal = wn * 16 + cq * 8 + 2 * (lane & 3);
                #pragma unroll
                for (int half = 0; half < 2; half++) {
                    int lrow = wm_ * 32 + rf * 16 + (lane >> 2) + half * 8;
                    float m0 = aM[rf][cq][half * 2 + 0];
                    float m1 = aM[rf][cq][half * 2 + 1];
                    float v0 = aV[rf][cq][half * 2 + 0];
                    float v1 = aV[rf][cq][half * 2 + 1];
                    bool g0 = m0 > 0.f, g1 = m1 > 0.f;
                    m0 = g0 ? m0 : 0.f;  v0 = g0 ? v0 : 0.f;
                    m1 = g1 ? m1 : 0.f;  v1 = g1 ? v1 : 0.f;
                    int o = lrow * P1B + klocal * 2;
                    *(uint32_t*)(sm + S_L1MH + o) =
                        pk(__float2bfloat16(m0), __float2bfloat16(m1));
                    *(uint32_t*)(sm + S_L1VH + o) =
                        pk(__float2bfloat16(v0), __float2bfloat16(v1));
                    *(uint32_t*)(sm + S_L12H + o) =
                        pk(__float2bfloat16(m0 * m0), __float2bfloat16(m1 * m1));
                }
            }
        }

        CP_WAIT(1);                      // W1[nc] arrived (W0[nc+1] may still fly)
        __syncthreads();

        // ---- layer1 MMA accumulate ---------------------------------------------
        #pragma unroll
        for (int ks = 0; ks < 2; ks++) {
            const int k = ks * 16;
            uint32_t Amh[2][4], Avh[2][4], A2m[2][4];
            #pragma unroll
            for (int rf = 0; rf < 2; rf++) {
                int ar = wm_ * 32 + rf * 16 + lr + (sel & 1) * 8;
                int ac = k + (sel >> 1) * 8;
                uint32_t off = (uint32_t)(ar * P1B + ac * 2);
                LDSM4(Amh[rf], sb + S_L1MH + off);
                LDSM4(Avh[rf], sb + S_L1VH + off);
                LDSM4(A2m[rf], sb + S_L12H + off);
            }
            uint32_t Bm[2][4], Bl[2][4], Ba[2][4], Bv[2][4];
            #pragma unroll
            for (int p = 0; p < 2; p++) {
                int br = wn * 32 + p * 16 + lr + (sel >> 1) * 8;
                int bc = k + (sel & 1) * 8;
                uint32_t off = (uint32_t)(br * P1B + bc * 2);
                LDSM4(Bm[p], sb + S_W1 + off);
                LDSM4(Bl[p], sb + S_W1 + W1_MAT + off);
                LDSM4(Ba[p], sb + S_W1 + 2 * W1_MAT + off);
                LDSM4(Bv[p], sb + S_W1 + 3 * W1_MAT + off);
            }
            #pragma unroll
            for (int rf = 0; rf < 2; rf++) {
                #pragma unroll
                for (int p = 0; p < 2; p++) {
                    #pragma unroll
                    for (int cq = 0; cq < 2; cq++) {
                        int cf = p * 2 + cq, o2 = cq * 2;
                        mma16816(accM1[rf][cf], Amh[rf], &Bm[p][o2]);
                        mma16816(accM1[rf][cf], Amh[rf], &Bl[p][o2]);
                        mma16816(accV1[rf][cf], Avh[rf], &Ba[p][o2]);
                        mma16816(accV1[rf][cf], A2m[rf], &Bv[p][o2]);
                    }
                }
            }
        }
        __syncthreads();                 // W1 + L1A buffers free for next chunk
    }

    // ---- epilogue: inv-variance weighting into smem staging --------------------
    float* sInv  = (float*)(sm + S_SINV);
    float* sMinv = (float*)(sm + S_SMINV);
    #pragma unroll
    for (int rf = 0; rf < 2; rf++) {
        #pragma unroll
        for (int cf = 0; cf < 4; cf++) {
            int col = wn * 32 + cf * 8 + 2 * (lane & 3);
            #pragma unroll
            for (int half = 0; half < 2; half++) {
                int lrow = wm_ * 32 + rf * 16 + (lane >> 2) + half * 8;
                float m0 = accM1[rf][cf][half * 2 + 0];
                float m1 = accM1[rf][cf][half * 2 + 1];
                float V0 = fmaxf(accV1[rf][cf][half * 2 + 0], EPS);
                float V1 = fmaxf(accV1[rf][cf][half * 2 + 1], EPS);
                float i0 = 1.f / V0, i1 = 1.f / V1;
                sInv[lrow * 65 + col]      = i0;
                sInv[lrow * 65 + col + 1]  = i1;
                sMinv[lrow * 65 + col]     = m0 * i0;
                sMinv[lrow * 65 + col + 1] = m1 * i1;
            }
        }
    }
    __syncthreads();

    // ---- block-level segmented reduce over sorted uids -> atomics ---------------
    const int* uids = (const int*)(sm + S_UID);
    int col = t & 63, grp = t >> 6;            // 4 groups x 32 rows
    float aI = 0.f, aM = 0.f;
    int cur = -1;
    for (int r0 = 0; r0 < 32; r0++) {
        int row = grp * 32 + r0;
        int uid = uids[row];
        if (uid != cur) {
            if (cur >= 0) {
                atomicAdd(&g_sum_inv[cur * D_OUT + col], aI);
                atomicAdd(&g_sum_minv[cur * D_OUT + col], aM);
            }
            cur = uid; aI = 0.f; aM = 0.f;
        }
        if (uid >= 0) {
            aI += sInv[row * 65 + col];
            aM += sMinv[row * 65 + col];
        }
    }
    if (cur >= 0) {
        atomicAdd(&g_sum_inv[cur * D_OUT + col], aI);
        atomicAdd(&g_sum_minv[cur * D_OUT + col], aM);
    }
}

// ---------------- finalize ----------------------------------------------------
__global__ __launch_bounds__(256) void finalize_kernel(float* __restrict__ out) {
    int id = blockIdx.x * 256 + threadIdx.x;
    if (id < U_DIM * D_OUT) {
        float var = 1.f / (g_sum_inv[id] + EPS);
        out[id]                 = g_sum_minv[id] * var;
        out[U_DIM * D_OUT + id] = var;
    }
}

// ---------------- launch -------------------------------------------------------
extern "C" void kernel_launch(void* const* d_in, const int* in_sizes, int n_in,
                              void* d_out, int out_size) {
    const float* X     = (const float*)d_in[0];
    const int*   X_idx = (const int*)d_in[1];
    const float* Wmu0  = (const float*)d_in[2];
    const float* Wlv0  = (const float*)d_in[3];
    const float* Wmu1  = (const float*)d_in[4];
    const float* Wlv1  = (const float*)d_in[5];
    float* out = (float*)d_out;
    (void)in_sizes; (void)n_in; (void)out_size;

    cudaFuncSetAttribute(fused_kernel, cudaFuncAttributeMaxDynamicSharedMemorySize,
                         SMEM_SZ);

    const int nBlocks = (N_ROWS + BM - 1) / BM;

    prep_kernel<<<(U_DIM * D_OUT + 255) / 256, 256>>>(Wmu0, Wlv0, Wmu1, Wlv1);
    fused_kernel<<<nBlocks, NTHR, SMEM_SZ>>>(X, X_idx);
    finalize_kernel<<<(U_DIM * D_OUT + 255) / 256, 256>>>(out);
}